// round 3
// baseline (speedup 1.0000x reference)
#include <cuda_runtime.h>
#include <math.h>

#define Bsz  2048
#define Tin  128
#define Fin  64
#define Hh   256
#define G3   768
#define OUTL 32
#define FCH  256

// ---------------- scratch (device globals; no allocation) ----------------
__device__ float g_hs[(size_t)Tin * Bsz * Hh];   // [t][b][h]  256 MB
__device__ float g_A [(size_t)Bsz * Tin];        // Wq . hs
__device__ float g_C [(size_t)Bsz * Tin];        // bq . hs
__device__ float g_prev[Bsz];
__device__ float g_ctx[(size_t)Bsz * Hh];
__device__ float g_hd [(size_t)Bsz * Hh];

__device__ __forceinline__ float sigm(float x)  { return __fdividef(1.f, 1.f + __expf(-x)); }
__device__ __forceinline__ float tanh_(float x) { return 2.f * sigm(2.f * x) - 1.f; }

// ---------------- shared GEMM micro-kernel ----------------
// CTA: 256 threads = 8 warps. Tile: 64 batch rows x 32 "u" columns, but for all
// 3 gates simultaneously (N = 3x32 = 96 strided output cols). Warp w owns rows
// [w*8, w*8+8); lane owns one u. Accums: 3 gates x 8 rows per thread.
struct SmemMM {
    float in_tile[32][65];   // [k][row], pad 65 -> conflict-free store+broadcast read
    float w_tile [32][96];   // [k][g*32+u]
};

__device__ __forceinline__ void mm_accum(
    const float* __restrict__ in, int ldin, int kdim,
    const float* __restrict__ W,  int ldw,
    int bm0, int u0, int tid, int warp, int lane,
    float (&a0)[8], float (&a1)[8], float (&a2)[8],
    SmemMM& s)
{
    for (int kb = 0; kb < kdim; kb += 32) {
        __syncthreads();
        // load 64 rows x 32 k of the input (coalesced over k)
        for (int idx = tid; idx < 64 * 32; idx += 256) {
            int k = idx & 31, row = idx >> 5;
            s.in_tile[k][row] = in[(size_t)(bm0 + row) * ldin + kb + k];
        }
        // load 96 x 32 weight tile (rows u0+u + g*256 of W)
        for (int idx = tid; idx < 96 * 32; idx += 256) {
            int k = idx & 31, j = idx >> 5;
            int g = j >> 5, u = j & 31;
            s.w_tile[k][j] = W[(size_t)(g * 256 + u0 + u) * ldw + kb + k];
        }
        __syncthreads();
#pragma unroll
        for (int k = 0; k < 32; ++k) {
            float w0 = s.w_tile[k][lane];
            float w1 = s.w_tile[k][32 + lane];
            float w2 = s.w_tile[k][64 + lane];
#pragma unroll
            for (int i = 0; i < 8; ++i) {
                float v = s.in_tile[k][(warp << 3) + i];
                a0[i] = fmaf(v, w0, a0[i]);
                a1[i] = fmaf(v, w1, a1[i]);
                a2[i] = fmaf(v, w2, a2[i]);
            }
        }
    }
}

// ---------------- encoder step: fused [x_t|h] GEMM + GRU pointwise ----------------
__global__ __launch_bounds__(256, 2)
void enc_step_kernel(const float* __restrict__ x, const float* __restrict__ h0,
                     const float* __restrict__ Wih, const float* __restrict__ Whh,
                     const float* __restrict__ bih, const float* __restrict__ bhh,
                     int t)
{
    __shared__ SmemMM s;
    int tid = threadIdx.x, warp = tid >> 5, lane = tid & 31;
    int bm0 = blockIdx.x * 64, u0 = blockIdx.y * 32;

    const float* h_prev = (t == 0) ? h0 : (g_hs + (size_t)(t - 1) * Bsz * Hh);
    float*       h_out  = g_hs + (size_t)t * Bsz * Hh;

    float ar[8] = {0}, az[8] = {0}, an[8] = {0};   // gi (x part)
    float br[8] = {0}, bz[8] = {0}, bn[8] = {0};   // gh (h part)

    mm_accum(x + (size_t)t * Fin, Tin * Fin, Fin, Wih, Fin,
             bm0, u0, tid, warp, lane, ar, az, an, s);
    mm_accum(h_prev, Hh, Hh, Whh, Hh,
             bm0, u0, tid, warp, lane, br, bz, bn, s);

    int u = u0 + lane;
    float bir = bih[u], biz = bih[256 + u], bin = bih[512 + u];
    float bhr = bhh[u], bhz = bhh[256 + u], bhn = bhh[512 + u];
#pragma unroll
    for (int i = 0; i < 8; ++i) {
        int b = bm0 + (warp << 3) + i;
        float r = sigm(ar[i] + bir + br[i] + bhr);
        float z = sigm(az[i] + biz + bz[i] + bhz);
        float n = tanh_(an[i] + bin + r * (bn[i] + bhn));
        float ho = h_prev[(size_t)b * Hh + u];
        h_out[(size_t)b * Hh + u] = (1.f - z) * n + z * ho;
    }
}

// ---------------- attention precompute: A = Wq.hs, C = bq.hs ----------------
__global__ __launch_bounds__(256)
void attn_pre_kernel(const float* __restrict__ Wq, const float* __restrict__ bq)
{
    int warp = threadIdx.x >> 5, lane = threadIdx.x & 31;
    int p = blockIdx.x * 8 + warp;           // p in [0, B*T)
    int b = p >> 7, t = p & 127;
    const float* hp = g_hs + ((size_t)t * Bsz + b) * Hh;
    float a = 0.f, c = 0.f;
#pragma unroll
    for (int j = 0; j < 8; ++j) {
        int h = lane + 32 * j;
        float v = hp[h];
        a = fmaf(Wq[h], v, a);
        c = fmaf(bq[h], v, c);
    }
#pragma unroll
    for (int off = 16; off > 0; off >>= 1) {
        a += __shfl_xor_sync(0xffffffffu, a, off);
        c += __shfl_xor_sync(0xffffffffu, c, off);
    }
    if (lane == 0) { g_A[(size_t)b * Tin + t] = a; g_C[(size_t)b * Tin + t] = c; }
}

__global__ void init_prev_kernel(const float* __restrict__ x)
{
    int i = blockIdx.x * 256 + threadIdx.x;
    if (i < Bsz) g_prev[i] = x[(size_t)i * Tin * Fin + (size_t)(Tin - 1) * Fin];
}

// ---------------- decoder: softmax (rank-1 scores) + ctx weighted sum ----------------
__global__ __launch_bounds__(256)
void dec_attn_kernel()
{
    __shared__ float wbuf[16][128];
    int tid = threadIdx.x, warp = tid >> 5, lane = tid & 31;
    int b0 = blockIdx.x * 16;
    const float scale = 0.0625f;   // 1/sqrt(256)

    for (int rr = warp; rr < 16; rr += 8) {
        int b = b0 + rr;
        float p = g_prev[b];
        float sv[4];
        float m = -1e30f;
#pragma unroll
        for (int j = 0; j < 4; ++j) {
            int t = lane + 32 * j;
            sv[j] = scale * fmaf(p, g_A[(size_t)b * Tin + t], g_C[(size_t)b * Tin + t]);
            m = fmaxf(m, sv[j]);
        }
#pragma unroll
        for (int off = 16; off > 0; off >>= 1)
            m = fmaxf(m, __shfl_xor_sync(0xffffffffu, m, off));
        float sum = 0.f;
#pragma unroll
        for (int j = 0; j < 4; ++j) { sv[j] = __expf(sv[j] - m); sum += sv[j]; }
#pragma unroll
        for (int off = 16; off > 0; off >>= 1)
            sum += __shfl_xor_sync(0xffffffffu, sum, off);
        float inv = 1.f / sum;
#pragma unroll
        for (int j = 0; j < 4; ++j) wbuf[rr][lane + 32 * j] = sv[j] * inv;
    }
    __syncthreads();

    // ctx[b][h] = sum_t w[b][t] * hs[t][b][h]; thread owns h = tid for 16 rows
    float acc[16];
#pragma unroll
    for (int r = 0; r < 16; ++r) acc[r] = 0.f;
    for (int t = 0; t < Tin; ++t) {
        const float* hp = g_hs + ((size_t)t * Bsz + b0) * Hh + tid;
#pragma unroll
        for (int r = 0; r < 16; ++r)
            acc[r] = fmaf(wbuf[r][t], hp[(size_t)r * Hh], acc[r]);
    }
#pragma unroll
    for (int r = 0; r < 16; ++r)
        g_ctx[(size_t)(b0 + r) * Hh + tid] = acc[r];
}

// ---------------- decoder GRU: gh = ctx @ Whh^T (rank-1 gi from prev) ----------------
__global__ __launch_bounds__(256, 2)
void dec_gru_kernel(const float* __restrict__ Wih1, const float* __restrict__ Whh,
                    const float* __restrict__ bih,  const float* __restrict__ bhh)
{
    __shared__ SmemMM s;
    int tid = threadIdx.x, warp = tid >> 5, lane = tid & 31;
    int bm0 = blockIdx.x * 64, u0 = blockIdx.y * 32;

    float br[8] = {0}, bz[8] = {0}, bn[8] = {0};
    mm_accum(g_ctx, Hh, Hh, Whh, Hh, bm0, u0, tid, warp, lane, br, bz, bn, s);

    int u = u0 + lane;
    float wir = Wih1[u], wiz = Wih1[256 + u], win = Wih1[512 + u];
    float bir = bih[u],  biz = bih[256 + u], bin = bih[512 + u];
    float bhr = bhh[u],  bhz = bhh[256 + u], bhn = bhh[512 + u];
#pragma unroll
    for (int i = 0; i < 8; ++i) {
        int b = bm0 + (warp << 3) + i;
        float p = g_prev[b];
        float r = sigm(fmaf(p, wir, bir) + br[i] + bhr);
        float z = sigm(fmaf(p, wiz, biz) + bz[i] + bhz);
        float n = tanh_(fmaf(p, win, bin) + r * (bn[i] + bhn));
        float c = g_ctx[(size_t)b * Hh + u];
        g_hd[(size_t)b * Hh + u] = (1.f - z) * n + z * c;
    }
}

// ---------------- decoder output: relu(hd@fc1^T+b) @ fc2^T + b ----------------
__global__ __launch_bounds__(256)
void dec_out_kernel(const float* __restrict__ fc1W, const float* __restrict__ fc1b,
                    const float* __restrict__ fc2W, const float* __restrict__ fc2b,
                    float* __restrict__ out, int step)
{
    __shared__ float hds[8][256];
    __shared__ float wsm[32][256];
    __shared__ float red[8][8];
    int tid = threadIdx.x, warp = tid >> 5, lane = tid & 31;
    int b0 = blockIdx.x * 8;

    for (int idx = tid; idx < 8 * 256; idx += 256) {
        int row = idx >> 8, k = idx & 255;
        hds[row][k] = g_hd[(size_t)(b0 + row) * 256 + k];
    }

    float acc[8] = {0, 0, 0, 0, 0, 0, 0, 0};
    for (int kb = 0; kb < 256; kb += 32) {
        __syncthreads();
        for (int idx = tid; idx < 32 * 256; idx += 256) {
            int j = idx >> 5, k = idx & 31;
            wsm[k][j] = fc1W[(size_t)j * 256 + kb + k];
        }
        __syncthreads();
#pragma unroll
        for (int k = 0; k < 32; ++k) {
            float wv = wsm[k][tid];
#pragma unroll
            for (int r = 0; r < 8; ++r)
                acc[r] = fmaf(hds[r][kb + k], wv, acc[r]);
        }
    }

    float b1 = fc1b[tid];
    float w2 = fc2W[tid];
#pragma unroll
    for (int r = 0; r < 8; ++r) {
        float v = fmaxf(acc[r] + b1, 0.f) * w2;
#pragma unroll
        for (int off = 16; off > 0; off >>= 1)
            v += __shfl_xor_sync(0xffffffffu, v, off);
        if (lane == 0) red[warp][r] = v;
    }
    __syncthreads();
    if (warp == 0 && lane < 8) {
        int r = lane;
        float ssum = 0.f;
#pragma unroll
        for (int w = 0; w < 8; ++w) ssum += red[w][r];
        ssum += fc2b[0];
        int b = b0 + r;
        out[(size_t)b * OUTL + step] = ssum;   // output layout (B, OUT_LEN)
        g_prev[b] = ssum;
    }
}

// ---------------- launch ----------------
extern "C" void kernel_launch(void* const* d_in, const int* in_sizes, int n_in,
                              void* d_out, int out_size)
{
    (void)in_sizes; (void)n_in; (void)out_size;
    const float* x    = (const float*)d_in[0];
    const float* h0   = (const float*)d_in[1];
    const float* eWih = (const float*)d_in[2];
    const float* eWhh = (const float*)d_in[3];
    const float* ebih = (const float*)d_in[4];
    const float* ebhh = (const float*)d_in[5];
    const float* dWih = (const float*)d_in[6];
    const float* dWhh = (const float*)d_in[7];
    const float* dbih = (const float*)d_in[8];
    const float* dbhh = (const float*)d_in[9];
    const float* aWq  = (const float*)d_in[10];
    const float* abq  = (const float*)d_in[11];
    const float* f1W  = (const float*)d_in[12];
    const float* f1b  = (const float*)d_in[13];
    const float* f2W  = (const float*)d_in[14];
    const float* f2b  = (const float*)d_in[15];
    float* out = (float*)d_out;

    dim3 gg(Bsz / 64, Hh / 32);   // (32, 8)

    for (int t = 0; t < Tin; ++t)
        enc_step_kernel<<<gg, 256>>>(x, h0, eWih, eWhh, ebih, ebhh, t);

    attn_pre_kernel<<<(Bsz * Tin) / 8, 256>>>(aWq, abq);
    init_prev_kernel<<<Bsz / 256, 256>>>(x);

    for (int s = 0; s < OUTL; ++s) {
        dec_attn_kernel<<<Bsz / 16, 256>>>();
        dec_gru_kernel<<<gg, 256>>>(dWih, dWhh, dbih, dbhh);
        dec_out_kernel<<<Bsz / 8, 256>>>(f1W, f1b, f2W, f2b, out, s);
    }
}

// round 4
// speedup vs baseline: 1.8777x; 1.8777x over previous
#include <cuda_runtime.h>
#include <math.h>

#define Bsz  2048
#define Tin  128
#define Fin  64
#define Hh   256
#define OUTL 32
#define FCH  256

typedef unsigned long long ull;

// ---------------- scratch (device globals; no allocation) ----------------
__device__ float g_hs[(size_t)Tin * Bsz * Hh];   // [t][b][h]
__device__ float g_A [(size_t)Bsz * Tin];        // Wq . hs
__device__ float g_C [(size_t)Bsz * Tin];        // bq . hs
__device__ float g_prev[Bsz];
__device__ float g_ctx[(size_t)Bsz * Hh];
__device__ float g_hd [(size_t)Bsz * Hh];

__device__ __forceinline__ float sigm(float x)  { return __fdividef(1.f, 1.f + __expf(-x)); }
__device__ __forceinline__ float tanh_(float x) { return 2.f * sigm(2.f * x) - 1.f; }

// ---------------- packed f32x2 helpers ----------------
__device__ __forceinline__ ull pk2(float lo, float hi) {
    ull r; asm("mov.b64 %0,{%1,%2};" : "=l"(r) : "f"(lo), "f"(hi)); return r;
}
__device__ __forceinline__ void upk2(ull v, float& lo, float& hi) {
    asm("mov.b64 {%0,%1},%2;" : "=f"(lo), "=f"(hi) : "l"(v));
}
__device__ __forceinline__ ull ffma2(ull a, ull b, ull c) {
    ull d; asm("fma.rn.f32x2 %0,%1,%2,%3;" : "=l"(d) : "l"(a), "l"(b), "l"(c)); return d;
}

// ---------------- shared GEMM micro-kernel (FFMA2) ----------------
// CTA: 128 threads = 4 warps. Tile: 32 batch rows x 64 u cols x 3 gates.
// warp w owns rows [w*8, w*8+8); lane owns u-pair (u0 + 2*lane, +1).
// Accumulators are packed f32x2 over the u-pair.
// in2 holds activations DUPLICATED ({v,v}) so the splat is free in the loop.
struct SmemG {
    float in2[32][68];    // [k][2*row + half], stride 68 -> 16B-aligned rows
    float wt [32][194];   // [k][g*64 + u],     stride 194 (2 pad)
};

__device__ __forceinline__ void mm2(
    const float* __restrict__ in, int ldin, int kdim,
    const float* __restrict__ W,  int ldw,  int u0,
    int tid, int warp, int lane,
    ull (&aR)[8], ull (&aZ)[8], ull (&aN)[8], SmemG& s)
{
    for (int kb = 0; kb < kdim; kb += 32) {
        __syncthreads();
        // activations: 32 rows x 32 k, float4 over k, duplicated store
#pragma unroll
        for (int it = 0; it < 2; ++it) {
            int idx = tid + it * 128;            // 0..255
            int kq = idx & 7, row = idx >> 3;
            float4 v = *(const float4*)(in + (size_t)row * ldin + kb + kq * 4);
            *(ull*)&s.in2[kq * 4 + 0][2 * row] = pk2(v.x, v.x);
            *(ull*)&s.in2[kq * 4 + 1][2 * row] = pk2(v.y, v.y);
            *(ull*)&s.in2[kq * 4 + 2][2 * row] = pk2(v.z, v.z);
            *(ull*)&s.in2[kq * 4 + 3][2 * row] = pk2(v.w, v.w);
        }
        // weights: 192 cols x 32 k, float4 over k
#pragma unroll
        for (int it = 0; it < 12; ++it) {
            int idx = tid + it * 128;            // 0..1535
            int kq = idx & 7, col = idx >> 3;
            int g = col >> 6, u = col & 63;
            float4 v = *(const float4*)(W + (size_t)(g * 256 + u0 + u) * ldw + kb + kq * 4);
            s.wt[kq * 4 + 0][col] = v.x;
            s.wt[kq * 4 + 1][col] = v.y;
            s.wt[kq * 4 + 2][col] = v.z;
            s.wt[kq * 4 + 3][col] = v.w;
        }
        __syncthreads();
#pragma unroll
        for (int k = 0; k < 32; ++k) {
            ull w0 = *(const ull*)&s.wt[k][      2 * lane];
            ull w1 = *(const ull*)&s.wt[k][ 64 + 2 * lane];
            ull w2 = *(const ull*)&s.wt[k][128 + 2 * lane];
            const float* ip = &s.in2[k][warp * 16];
            ulonglong2 pA = *(const ulonglong2*)(ip + 0);
            ulonglong2 pB = *(const ulonglong2*)(ip + 4);
            ulonglong2 pC = *(const ulonglong2*)(ip + 8);
            ulonglong2 pD = *(const ulonglong2*)(ip + 12);
            ull v[8] = { pA.x, pA.y, pB.x, pB.y, pC.x, pC.y, pD.x, pD.y };
#pragma unroll
            for (int i = 0; i < 8; ++i) {
                aR[i] = ffma2(v[i], w0, aR[i]);
                aZ[i] = ffma2(v[i], w1, aZ[i]);
                aN[i] = ffma2(v[i], w2, aN[i]);
            }
        }
    }
}

// ---------------- encoder step: fused [x_t|h] GEMM + GRU pointwise ----------------
__global__ __launch_bounds__(128, 3)
void enc_step_kernel(const float* __restrict__ x, const float* __restrict__ h0,
                     const float* __restrict__ Wih, const float* __restrict__ Whh,
                     const float* __restrict__ bih, const float* __restrict__ bhh,
                     int t)
{
    __shared__ SmemG s;
    int tid = threadIdx.x, warp = tid >> 5, lane = tid & 31;
    int bm0 = blockIdx.x * 32, u0 = blockIdx.y * 64;

    const float* h_prev = (t == 0) ? h0 : (g_hs + (size_t)(t - 1) * Bsz * Hh);
    float*       h_out  = g_hs + (size_t)t * Bsz * Hh;

    ull aR[8] = {0}, aZ[8] = {0}, aNX[8] = {0}, aNH[8] = {0};

    mm2(x + (size_t)t * Fin + (size_t)bm0 * Tin * Fin, Tin * Fin, Fin,
        Wih, Fin, u0, tid, warp, lane, aR, aZ, aNX, s);
    mm2(h_prev + (size_t)bm0 * Hh, Hh, Hh,
        Whh, Hh, u0, tid, warp, lane, aR, aZ, aNH, s);

    int u = u0 + 2 * lane;
    float2 bir = *(const float2*)&bih[u];
    float2 biz = *(const float2*)&bih[256 + u];
    float2 bin = *(const float2*)&bih[512 + u];
    float2 bhr = *(const float2*)&bhh[u];
    float2 bhz = *(const float2*)&bhh[256 + u];
    float2 bhn = *(const float2*)&bhh[512 + u];
#pragma unroll
    for (int i = 0; i < 8; ++i) {
        int b = bm0 + (warp << 3) + i;
        float r0, r1, z0, z1, nx0, nx1, nh0, nh1;
        upk2(aR[i], r0, r1);  upk2(aZ[i], z0, z1);
        upk2(aNX[i], nx0, nx1); upk2(aNH[i], nh0, nh1);
        float2 hp = *(const float2*)&h_prev[(size_t)b * Hh + u];
        float rr0 = sigm(r0 + bir.x + bhr.x);
        float rr1 = sigm(r1 + bir.y + bhr.y);
        float zz0 = sigm(z0 + biz.x + bhz.x);
        float zz1 = sigm(z1 + biz.y + bhz.y);
        float nn0 = tanh_(nx0 + bin.x + rr0 * (nh0 + bhn.x));
        float nn1 = tanh_(nx1 + bin.y + rr1 * (nh1 + bhn.y));
        float2 o;
        o.x = (1.f - zz0) * nn0 + zz0 * hp.x;
        o.y = (1.f - zz1) * nn1 + zz1 * hp.y;
        *(float2*)&h_out[(size_t)b * Hh + u] = o;
    }
}

// ---------------- attention precompute: A = Wq.hs, C = bq.hs ----------------
__global__ __launch_bounds__(256)
void attn_pre_kernel(const float* __restrict__ Wq, const float* __restrict__ bq)
{
    int warp = threadIdx.x >> 5, lane = threadIdx.x & 31;
    int p = blockIdx.x * 8 + warp;           // p in [0, B*T)
    int b = p >> 7, t = p & 127;
    const float* hp = g_hs + ((size_t)t * Bsz + b) * Hh;
    float a = 0.f, c = 0.f;
#pragma unroll
    for (int j = 0; j < 8; ++j) {
        int h = lane + 32 * j;
        float v = hp[h];
        a = fmaf(Wq[h], v, a);
        c = fmaf(bq[h], v, c);
    }
#pragma unroll
    for (int off = 16; off > 0; off >>= 1) {
        a += __shfl_xor_sync(0xffffffffu, a, off);
        c += __shfl_xor_sync(0xffffffffu, c, off);
    }
    if (lane == 0) { g_A[(size_t)b * Tin + t] = a; g_C[(size_t)b * Tin + t] = c; }
}

__global__ void init_prev_kernel(const float* __restrict__ x)
{
    int i = blockIdx.x * 256 + threadIdx.x;
    if (i < Bsz) g_prev[i] = x[(size_t)i * Tin * Fin + (size_t)(Tin - 1) * Fin];
}

// ---------------- decoder: softmax (rank-1 scores) + ctx weighted sum ----------------
// 8 batch rows per CTA -> 256 CTAs, full-chip DRAM streaming of hs.
__global__ __launch_bounds__(256)
void dec_attn_kernel()
{
    __shared__ float wbuf[8][128];
    int tid = threadIdx.x, warp = tid >> 5, lane = tid & 31;
    int b0 = blockIdx.x * 8;
    const float scale = 0.0625f;   // 1/sqrt(256)

    {
        int b = b0 + warp;
        float p = g_prev[b];
        float sv[4];
        float m = -1e30f;
#pragma unroll
        for (int j = 0; j < 4; ++j) {
            int t = lane + 32 * j;
            sv[j] = scale * fmaf(p, g_A[(size_t)b * Tin + t], g_C[(size_t)b * Tin + t]);
            m = fmaxf(m, sv[j]);
        }
#pragma unroll
        for (int off = 16; off > 0; off >>= 1)
            m = fmaxf(m, __shfl_xor_sync(0xffffffffu, m, off));
        float sum = 0.f;
#pragma unroll
        for (int j = 0; j < 4; ++j) { sv[j] = __expf(sv[j] - m); sum += sv[j]; }
#pragma unroll
        for (int off = 16; off > 0; off >>= 1)
            sum += __shfl_xor_sync(0xffffffffu, sum, off);
        float inv = 1.f / sum;
#pragma unroll
        for (int j = 0; j < 4; ++j) wbuf[warp][lane + 32 * j] = sv[j] * inv;
    }
    __syncthreads();

    // ctx[b][h] = sum_t w[b][t] * hs[t][b][h]; thread owns h = tid for 8 rows
    float acc[8];
#pragma unroll
    for (int r = 0; r < 8; ++r) acc[r] = 0.f;
#pragma unroll 2
    for (int t = 0; t < Tin; ++t) {
        const float* hp = g_hs + ((size_t)t * Bsz + b0) * Hh + tid;
#pragma unroll
        for (int r = 0; r < 8; ++r)
            acc[r] = fmaf(wbuf[r][t], hp[(size_t)r * Hh], acc[r]);
    }
#pragma unroll
    for (int r = 0; r < 8; ++r)
        g_ctx[(size_t)(b0 + r) * Hh + tid] = acc[r];
}

// ---------------- decoder GRU: gh = ctx @ Whh^T (rank-1 gi from prev) ----------------
__global__ __launch_bounds__(128, 3)
void dec_gru_kernel(const float* __restrict__ Wih1, const float* __restrict__ Whh,
                    const float* __restrict__ bih,  const float* __restrict__ bhh)
{
    __shared__ SmemG s;
    int tid = threadIdx.x, warp = tid >> 5, lane = tid & 31;
    int bm0 = blockIdx.x * 32, u0 = blockIdx.y * 64;

    ull aR[8] = {0}, aZ[8] = {0}, aN[8] = {0};
    mm2(g_ctx + (size_t)bm0 * Hh, Hh, Hh, Whh, Hh, u0, tid, warp, lane, aR, aZ, aN, s);

    int u = u0 + 2 * lane;
    float2 wir = *(const float2*)&Wih1[u];
    float2 wiz = *(const float2*)&Wih1[256 + u];
    float2 win = *(const float2*)&Wih1[512 + u];
    float2 bir = *(const float2*)&bih[u];
    float2 biz = *(const float2*)&bih[256 + u];
    float2 bin = *(const float2*)&bih[512 + u];
    float2 bhr = *(const float2*)&bhh[u];
    float2 bhz = *(const float2*)&bhh[256 + u];
    float2 bhn = *(const float2*)&bhh[512 + u];
#pragma unroll
    for (int i = 0; i < 8; ++i) {
        int b = bm0 + (warp << 3) + i;
        float p = g_prev[b];
        float hr0, hr1, hz0, hz1, hn0, hn1;
        upk2(aR[i], hr0, hr1); upk2(aZ[i], hz0, hz1); upk2(aN[i], hn0, hn1);
        float2 c = *(const float2*)&g_ctx[(size_t)b * Hh + u];
        float r0 = sigm(fmaf(p, wir.x, bir.x) + hr0 + bhr.x);
        float r1 = sigm(fmaf(p, wir.y, bir.y) + hr1 + bhr.y);
        float z0 = sigm(fmaf(p, wiz.x, biz.x) + hz0 + bhz.x);
        float z1 = sigm(fmaf(p, wiz.y, biz.y) + hz1 + bhz.y);
        float n0 = tanh_(fmaf(p, win.x, bin.x) + r0 * (hn0 + bhn.x));
        float n1 = tanh_(fmaf(p, win.y, bin.y) + r1 * (hn1 + bhn.y));
        float2 o;
        o.x = (1.f - z0) * n0 + z0 * c.x;
        o.y = (1.f - z1) * n1 + z1 * c.y;
        *(float2*)&g_hd[(size_t)b * Hh + u] = o;
    }
}

// ---------------- decoder output: relu(hd@fc1^T+b) @ fc2^T + b ----------------
__global__ __launch_bounds__(256)
void dec_out_kernel(const float* __restrict__ fc1W, const float* __restrict__ fc1b,
                    const float* __restrict__ fc2W, const float* __restrict__ fc2b,
                    float* __restrict__ out, int step)
{
    __shared__ float hds[8][256];
    __shared__ float wsm[32][256];
    __shared__ float red[8][8];
    int tid = threadIdx.x, warp = tid >> 5, lane = tid & 31;
    int b0 = blockIdx.x * 8;

    for (int idx = tid; idx < 8 * 256; idx += 256) {
        int row = idx >> 8, k = idx & 255;
        hds[row][k] = g_hd[(size_t)(b0 + row) * 256 + k];
    }

    float acc[8] = {0, 0, 0, 0, 0, 0, 0, 0};
    for (int kb = 0; kb < 256; kb += 32) {
        __syncthreads();
        for (int idx = tid; idx < 32 * 256; idx += 256) {
            int j = idx >> 5, k = idx & 31;
            wsm[k][j] = fc1W[(size_t)j * 256 + kb + k];
        }
        __syncthreads();
#pragma unroll
        for (int k = 0; k < 32; ++k) {
            float wv = wsm[k][tid];
#pragma unroll
            for (int r = 0; r < 8; ++r)
                acc[r] = fmaf(hds[r][kb + k], wv, acc[r]);
        }
    }

    float b1 = fc1b[tid];
    float w2 = fc2W[tid];
#pragma unroll
    for (int r = 0; r < 8; ++r) {
        float v = fmaxf(acc[r] + b1, 0.f) * w2;
#pragma unroll
        for (int off = 16; off > 0; off >>= 1)
            v += __shfl_xor_sync(0xffffffffu, v, off);
        if (lane == 0) red[warp][r] = v;
    }
    __syncthreads();
    if (warp == 0 && lane < 8) {
        int r = lane;
        float ssum = 0.f;
#pragma unroll
        for (int w = 0; w < 8; ++w) ssum += red[w][r];
        ssum += fc2b[0];
        int b = b0 + r;
        out[(size_t)b * OUTL + step] = ssum;   // output layout (B, OUT_LEN)
        g_prev[b] = ssum;
    }
}

// ---------------- launch ----------------
extern "C" void kernel_launch(void* const* d_in, const int* in_sizes, int n_in,
                              void* d_out, int out_size)
{
    (void)in_sizes; (void)n_in; (void)out_size;
    const float* x    = (const float*)d_in[0];
    const float* h0   = (const float*)d_in[1];
    const float* eWih = (const float*)d_in[2];
    const float* eWhh = (const float*)d_in[3];
    const float* ebih = (const float*)d_in[4];
    const float* ebhh = (const float*)d_in[5];
    const float* dWih = (const float*)d_in[6];
    const float* dWhh = (const float*)d_in[7];
    const float* dbih = (const float*)d_in[8];
    const float* dbhh = (const float*)d_in[9];
    const float* aWq  = (const float*)d_in[10];
    const float* abq  = (const float*)d_in[11];
    const float* f1W  = (const float*)d_in[12];
    const float* f1b  = (const float*)d_in[13];
    const float* f2W  = (const float*)d_in[14];
    const float* f2b  = (const float*)d_in[15];
    float* out = (float*)d_out;

    dim3 gg(Bsz / 32, Hh / 64);   // (64, 4) = 256 CTAs, 128 threads

    for (int t = 0; t < Tin; ++t)
        enc_step_kernel<<<gg, 128>>>(x, h0, eWih, eWhh, ebih, ebhh, t);

    attn_pre_kernel<<<(Bsz * Tin) / 8, 256>>>(aWq, abq);
    init_prev_kernel<<<Bsz / 256, 256>>>(x);

    for (int s = 0; s < OUTL; ++s) {
        dec_attn_kernel<<<Bsz / 8, 256>>>();
        dec_gru_kernel<<<gg, 128>>>(dWih, dWhh, dbih, dbhh);
        dec_out_kernel<<<Bsz / 8, 256>>>(f1W, f1b, f2W, f2b, out, s);
    }
}

// round 7
// speedup vs baseline: 1.8837x; 1.0032x over previous
#include <cuda_runtime.h>
#include <math.h>

#define Bsz  2048
#define Tin  128
#define Fin  64
#define Hh   256
#define OUTL 32
#define FCH  256

typedef unsigned long long ull;

// ---------------- scratch (device globals; no allocation) ----------------
__device__ float g_hs[(size_t)Tin * Bsz * Hh];   // [t][b][h]
__device__ float g_A [(size_t)Bsz * Tin];        // Wq . hs
__device__ float g_C [(size_t)Bsz * Tin];        // bq . hs
__device__ float g_prev[Bsz];
__device__ float g_ctx[(size_t)Bsz * Hh];
__device__ float g_hd [(size_t)Bsz * Hh];

__device__ __forceinline__ float sigm(float x)  { return __fdividef(1.f, 1.f + __expf(-x)); }
__device__ __forceinline__ float tanh_(float x) { return 2.f * sigm(2.f * x) - 1.f; }

// ---------------- packed f32x2 helpers ----------------
__device__ __forceinline__ ull pk2(float lo, float hi) {
    ull r; asm("mov.b64 %0,{%1,%2};" : "=l"(r) : "f"(lo), "f"(hi)); return r;
}
__device__ __forceinline__ void upk2(ull v, float& lo, float& hi) {
    asm("mov.b64 {%0,%1},%2;" : "=f"(lo), "=f"(hi) : "l"(v));
}
__device__ __forceinline__ ull ffma2(ull a, ull b, ull c) {
    ull d; asm("fma.rn.f32x2 %0,%1,%2,%3;" : "=l"(d) : "l"(a), "l"(b), "l"(c)); return d;
}

// ---------------- shared GEMM micro-kernel (FFMA2) ----------------
// CTA: 128 threads = 4 warps. Tile: 32 batch rows x 64 u cols x 3 gates.
// warp w owns rows [w*8, w*8+8); lane owns u-pair (u0 + 2*lane, +1).
// Accumulators are packed f32x2 over the u-pair.
// in2 holds activations DUPLICATED ({v,v}) so the splat is free in the loop.
struct SmemG {
    float in2[32][68];    // [k][2*row + half], stride 68 -> 16B-aligned rows
    float wt [32][194];   // [k][g*64 + u],     stride 194 (2 pad)
};

__device__ __forceinline__ void mm2(
    const float* __restrict__ in, int ldin, int kdim,
    const float* __restrict__ W,  int ldw,  int u0,
    int tid, int warp, int lane,
    ull (&aR)[8], ull (&aZ)[8], ull (&aN)[8], SmemG& s)
{
    for (int kb = 0; kb < kdim; kb += 32) {
        __syncthreads();
        // activations: 32 rows x 32 k, float4 over k, duplicated store
#pragma unroll
        for (int it = 0; it < 2; ++it) {
            int idx = tid + it * 128;            // 0..255
            int kq = idx & 7, row = idx >> 3;
            float4 v = *(const float4*)(in + (size_t)row * ldin + kb + kq * 4);
            *(ull*)&s.in2[kq * 4 + 0][2 * row] = pk2(v.x, v.x);
            *(ull*)&s.in2[kq * 4 + 1][2 * row] = pk2(v.y, v.y);
            *(ull*)&s.in2[kq * 4 + 2][2 * row] = pk2(v.z, v.z);
            *(ull*)&s.in2[kq * 4 + 3][2 * row] = pk2(v.w, v.w);
        }
        // weights: 192 cols x 32 k, float4 over k
#pragma unroll
        for (int it = 0; it < 12; ++it) {
            int idx = tid + it * 128;            // 0..1535
            int kq = idx & 7, col = idx >> 3;
            int g = col >> 6, u = col & 63;
            float4 v = *(const float4*)(W + (size_t)(g * 256 + u0 + u) * ldw + kb + kq * 4);
            s.wt[kq * 4 + 0][col] = v.x;
            s.wt[kq * 4 + 1][col] = v.y;
            s.wt[kq * 4 + 2][col] = v.z;
            s.wt[kq * 4 + 3][col] = v.w;
        }
        __syncthreads();
#pragma unroll
        for (int k = 0; k < 32; ++k) {
            ull w0 = *(const ull*)&s.wt[k][      2 * lane];
            ull w1 = *(const ull*)&s.wt[k][ 64 + 2 * lane];
            ull w2 = *(const ull*)&s.wt[k][128 + 2 * lane];
            const float* ip = &s.in2[k][warp * 16];
            ulonglong2 pA = *(const ulonglong2*)(ip + 0);
            ulonglong2 pB = *(const ulonglong2*)(ip + 4);
            ulonglong2 pC = *(const ulonglong2*)(ip + 8);
            ulonglong2 pD = *(const ulonglong2*)(ip + 12);
            ull v[8] = { pA.x, pA.y, pB.x, pB.y, pC.x, pC.y, pD.x, pD.y };
#pragma unroll
            for (int i = 0; i < 8; ++i) {
                aR[i] = ffma2(v[i], w0, aR[i]);
                aZ[i] = ffma2(v[i], w1, aZ[i]);
                aN[i] = ffma2(v[i], w2, aN[i]);
            }
        }
    }
}

// ---------------- encoder step: fused [x_t|h] GEMM + GRU pointwise ----------------
__global__ __launch_bounds__(128, 3)
void enc_step_kernel(const float* __restrict__ x, const float* __restrict__ h0,
                     const float* __restrict__ Wih, const float* __restrict__ Whh,
                     const float* __restrict__ bih, const float* __restrict__ bhh,
                     int t)
{
    __shared__ SmemG s;
    int tid = threadIdx.x, warp = tid >> 5, lane = tid & 31;
    int bm0 = blockIdx.x * 32, u0 = blockIdx.y * 64;

    const float* h_prev = (t == 0) ? h0 : (g_hs + (size_t)(t - 1) * Bsz * Hh);
    float*       h_out  = g_hs + (size_t)t * Bsz * Hh;

    ull aR[8] = {0}, aZ[8] = {0}, aNX[8] = {0}, aNH[8] = {0};

    mm2(x + (size_t)t * Fin + (size_t)bm0 * Tin * Fin, Tin * Fin, Fin,
        Wih, Fin, u0, tid, warp, lane, aR, aZ, aNX, s);
    mm2(h_prev + (size_t)bm0 * Hh, Hh, Hh,
        Whh, Hh, u0, tid, warp, lane, aR, aZ, aNH, s);

    int u = u0 + 2 * lane;
    float2 bir = *(const float2*)&bih[u];
    float2 biz = *(const float2*)&bih[256 + u];
    float2 bin = *(const float2*)&bih[512 + u];
    float2 bhr = *(const float2*)&bhh[u];
    float2 bhz = *(const float2*)&bhh[256 + u];
    float2 bhn = *(const float2*)&bhh[512 + u];
#pragma unroll
    for (int i = 0; i < 8; ++i) {
        int b = bm0 + (warp << 3) + i;
        float r0, r1, z0, z1, nx0, nx1, nh0, nh1;
        upk2(aR[i], r0, r1);  upk2(aZ[i], z0, z1);
        upk2(aNX[i], nx0, nx1); upk2(aNH[i], nh0, nh1);
        float2 hp = *(const float2*)&h_prev[(size_t)b * Hh + u];
        float rr0 = sigm(r0 + bir.x + bhr.x);
        float rr1 = sigm(r1 + bir.y + bhr.y);
        float zz0 = sigm(z0 + biz.x + bhz.x);
        float zz1 = sigm(z1 + biz.y + bhz.y);
        float nn0 = tanh_(nx0 + bin.x + rr0 * (nh0 + bhn.x));
        float nn1 = tanh_(nx1 + bin.y + rr1 * (nh1 + bhn.y));
        float2 o;
        o.x = (1.f - zz0) * nn0 + zz0 * hp.x;
        o.y = (1.f - zz1) * nn1 + zz1 * hp.y;
        *(float2*)&h_out[(size_t)b * Hh + u] = o;
    }
}

// ---------------- attention precompute: A = Wq.hs, C = bq.hs ----------------
__global__ __launch_bounds__(256)
void attn_pre_kernel(const float* __restrict__ Wq, const float* __restrict__ bq)
{
    int warp = threadIdx.x >> 5, lane = threadIdx.x & 31;
    int p = blockIdx.x * 8 + warp;           // p in [0, B*T)
    int b = p >> 7, t = p & 127;
    const float* hp = g_hs + ((size_t)t * Bsz + b) * Hh;
    float a = 0.f, c = 0.f;
#pragma unroll
    for (int j = 0; j < 8; ++j) {
        int h = lane + 32 * j;
        float v = hp[h];
        a = fmaf(Wq[h], v, a);
        c = fmaf(bq[h], v, c);
    }
#pragma unroll
    for (int off = 16; off > 0; off >>= 1) {
        a += __shfl_xor_sync(0xffffffffu, a, off);
        c += __shfl_xor_sync(0xffffffffu, c, off);
    }
    if (lane == 0) { g_A[(size_t)b * Tin + t] = a; g_C[(size_t)b * Tin + t] = c; }
}

__global__ void init_prev_kernel(const float* __restrict__ x)
{
    int i = blockIdx.x * 256 + threadIdx.x;
    if (i < Bsz) g_prev[i] = x[(size_t)i * Tin * Fin + (size_t)(Tin - 1) * Fin];
}

// ---------------- decoder: softmax (rank-1 scores) + ctx weighted sum ----------------
// 8 batch rows per CTA -> 256 CTAs, full-chip DRAM streaming of hs.
__global__ __launch_bounds__(256)
void dec_attn_kernel()
{
    __shared__ float wbuf[8][128];
    int tid = threadIdx.x, warp = tid >> 5, lane = tid & 31;
    int b0 = blockIdx.x * 8;
    const float scale = 0.0625f;   // 1/sqrt(256)

    {
        int b = b0 + warp;
        float p = g_prev[b];
        float sv[4];
        float m = -1e30f;
#pragma unroll
        for (int j = 0; j < 4; ++j) {
            int t = lane + 32 * j;
            sv[j] = scale * fmaf(p, g_A[(size_t)b * Tin + t], g_C[(size_t)b * Tin + t]);
            m = fmaxf(m, sv[j]);
        }
#pragma unroll
        for (int off = 16; off > 0; off >>= 1)
            m = fmaxf(m, __shfl_xor_sync(0xffffffffu, m, off));
        float sum = 0.f;
#pragma unroll
        for (int j = 0; j < 4; ++j) { sv[j] = __expf(sv[j] - m); sum += sv[j]; }
#pragma unroll
        for (int off = 16; off > 0; off >>= 1)
            sum += __shfl_xor_sync(0xffffffffu, sum, off);
        float inv = 1.f / sum;
#pragma unroll
        for (int j = 0; j < 4; ++j) wbuf[warp][lane + 32 * j] = sv[j] * inv;
    }
    __syncthreads();

    // ctx[b][h] = sum_t w[b][t] * hs[t][b][h]; thread owns h = tid for 8 rows
    float acc[8];
#pragma unroll
    for (int r = 0; r < 8; ++r) acc[r] = 0.f;
#pragma unroll 2
    for (int t = 0; t < Tin; ++t) {
        const float* hp = g_hs + ((size_t)t * Bsz + b0) * Hh + tid;
#pragma unroll
        for (int r = 0; r < 8; ++r)
            acc[r] = fmaf(wbuf[r][t], hp[(size_t)r * Hh], acc[r]);
    }
#pragma unroll
    for (int r = 0; r < 8; ++r)
        g_ctx[(size_t)(b0 + r) * Hh + tid] = acc[r];
}

// ---------------- decoder GRU: gh = ctx @ Whh^T (rank-1 gi from prev) ----------------
__global__ __launch_bounds__(128, 3)
void dec_gru_kernel(const float* __restrict__ Wih1, const float* __restrict__ Whh,
                    const float* __restrict__ bih,  const float* __restrict__ bhh)
{
    __shared__ SmemG s;
    int tid = threadIdx.x, warp = tid >> 5, lane = tid & 31;
    int bm0 = blockIdx.x * 32, u0 = blockIdx.y * 64;

    ull aR[8] = {0}, aZ[8] = {0}, aN[8] = {0};
    mm2(g_ctx + (size_t)bm0 * Hh, Hh, Hh, Whh, Hh, u0, tid, warp, lane, aR, aZ, aN, s);

    int u = u0 + 2 * lane;
    float2 wir = *(const float2*)&Wih1[u];
    float2 wiz = *(const float2*)&Wih1[256 + u];
    float2 win = *(const float2*)&Wih1[512 + u];
    float2 bir = *(const float2*)&bih[u];
    float2 biz = *(const float2*)&bih[256 + u];
    float2 bin = *(const float2*)&bih[512 + u];
    float2 bhr = *(const float2*)&bhh[u];
    float2 bhz = *(const float2*)&bhh[256 + u];
    float2 bhn = *(const float2*)&bhh[512 + u];
#pragma unroll
    for (int i = 0; i < 8; ++i) {
        int b = bm0 + (warp << 3) + i;
        float p = g_prev[b];
        float hr0, hr1, hz0, hz1, hn0, hn1;
        upk2(aR[i], hr0, hr1); upk2(aZ[i], hz0, hz1); upk2(aN[i], hn0, hn1);
        float2 c = *(const float2*)&g_ctx[(size_t)b * Hh + u];
        float r0 = sigm(fmaf(p, wir.x, bir.x) + hr0 + bhr.x);
        float r1 = sigm(fmaf(p, wir.y, bir.y) + hr1 + bhr.y);
        float z0 = sigm(fmaf(p, wiz.x, biz.x) + hz0 + bhz.x);
        float z1 = sigm(fmaf(p, wiz.y, biz.y) + hz1 + bhz.y);
        float n0 = tanh_(fmaf(p, win.x, bin.x) + r0 * (hn0 + bhn.x));
        float n1 = tanh_(fmaf(p, win.y, bin.y) + r1 * (hn1 + bhn.y));
        float2 o;
        o.x = (1.f - z0) * n0 + z0 * c.x;
        o.y = (1.f - z1) * n1 + z1 * c.y;
        *(float2*)&g_hd[(size_t)b * Hh + u] = o;
    }
}

// ---------------- decoder output: relu(hd@fc1^T+b) @ fc2^T + b ----------------
__global__ __launch_bounds__(256)
void dec_out_kernel(const float* __restrict__ fc1W, const float* __restrict__ fc1b,
                    const float* __restrict__ fc2W, const float* __restrict__ fc2b,
                    float* __restrict__ out, int step)
{
    __shared__ float hds[8][256];
    __shared__ float wsm[32][256];
    __shared__ float red[8][8];
    int tid = threadIdx.x, warp = tid >> 5, lane = tid & 31;
    int b0 = blockIdx.x * 8;

    for (int idx = tid; idx < 8 * 256; idx += 256) {
        int row = idx >> 8, k = idx & 255;
        hds[row][k] = g_hd[(size_t)(b0 + row) * 256 + k];
    }

    float acc[8] = {0, 0, 0, 0, 0, 0, 0, 0};
    for (int kb = 0; kb < 256; kb += 32) {
        __syncthreads();
        for (int idx = tid; idx < 32 * 256; idx += 256) {
            int j = idx >> 5, k = idx & 31;
            wsm[k][j] = fc1W[(size_t)j * 256 + kb + k];
        }
        __syncthreads();
#pragma unroll
        for (int k = 0; k < 32; ++k) {
            float wv = wsm[k][tid];
#pragma unroll
            for (int r = 0; r < 8; ++r)
                acc[r] = fmaf(hds[r][kb + k], wv, acc[r]);
        }
    }

    float b1 = fc1b[tid];
    float w2 = fc2W[tid];
#pragma unroll
    for (int r = 0; r < 8; ++r) {
        float v = fmaxf(acc[r] + b1, 0.f) * w2;
#pragma unroll
        for (int off = 16; off > 0; off >>= 1)
            v += __shfl_xor_sync(0xffffffffu, v, off);
        if (lane == 0) red[warp][r] = v;
    }
    __syncthreads();
    if (warp == 0 && lane < 8) {
        int r = lane;
        float ssum = 0.f;
#pragma unroll
        for (int w = 0; w < 8; ++w) ssum += red[w][r];
        ssum += fc2b[0];
        int b = b0 + r;
        out[(size_t)b * OUTL + step] = ssum;   // output layout (B, OUT_LEN)
        g_prev[b] = ssum;
    }
}

// ---------------- launch ----------------
extern "C" void kernel_launch(void* const* d_in, const int* in_sizes, int n_in,
                              void* d_out, int out_size)
{
    (void)in_sizes; (void)n_in; (void)out_size;
    const float* x    = (const float*)d_in[0];
    const float* h0   = (const float*)d_in[1];
    const float* eWih = (const float*)d_in[2];
    const float* eWhh = (const float*)d_in[3];
    const float* ebih = (const float*)d_in[4];
    const float* ebhh = (const float*)d_in[5];
    const float* dWih = (const float*)d_in[6];
    const float* dWhh = (const float*)d_in[7];
    const float* dbih = (const float*)d_in[8];
    const float* dbhh = (const float*)d_in[9];
    const float* aWq  = (const float*)d_in[10];
    const float* abq  = (const float*)d_in[11];
    const float* f1W  = (const float*)d_in[12];
    const float* f1b  = (const float*)d_in[13];
    const float* f2W  = (const float*)d_in[14];
    const float* f2b  = (const float*)d_in[15];
    float* out = (float*)d_out;

    dim3 gg(Bsz / 32, Hh / 64);   // (64, 4) = 256 CTAs, 128 threads

    for (int t = 0; t < Tin; ++t)
        enc_step_kernel<<<gg, 128>>>(x, h0, eWih, eWhh, ebih, ebhh, t);

    attn_pre_kernel<<<(Bsz * Tin) / 8, 256>>>(aWq, abq);
    init_prev_kernel<<<Bsz / 256, 256>>>(x);

    for (int s = 0; s < OUTL; ++s) {
        dec_attn_kernel<<<Bsz / 8, 256>>>();
        dec_gru_kernel<<<gg, 128>>>(dWih, dWhh, dbih, dbhh);
        dec_out_kernel<<<Bsz / 8, 256>>>(f1W, f1b, f2W, f2b, out, s);
    }
}

// round 8
// speedup vs baseline: 2.1668x; 1.1503x over previous
#include <cuda_runtime.h>
#include <cuda_fp16.h>
#include <math.h>

#define Bsz  2048
#define Tin  128
#define Fin  64
#define Hh   256
#define OUTL 32
#define FCH  256

typedef unsigned long long ull;

// ---------------- scratch (device globals; no allocation) ----------------
__device__ float  g_hs  [(size_t)Tin * Bsz * Hh];  // fp32 [t][b][h]
__device__ __half g_hs_h[(size_t)Tin * Bsz * Hh];  // fp16 copy (decoder stream)
__device__ float  g_A [(size_t)Bsz * Tin];
__device__ float  g_C [(size_t)Bsz * Tin];
__device__ float  g_prev[Bsz];
__device__ float  g_ctx[(size_t)Bsz * Hh];
__device__ float  g_hd [(size_t)Bsz * Hh];

__device__ __forceinline__ float sigm(float x)  { return __fdividef(1.f, 1.f + __expf(-x)); }
__device__ __forceinline__ float tanh_(float x) { return 2.f * sigm(2.f * x) - 1.f; }

__device__ __forceinline__ ull pk2(float lo, float hi) {
    ull r; asm("mov.b64 %0,{%1,%2};" : "=l"(r) : "f"(lo), "f"(hi)); return r;
}
__device__ __forceinline__ void upk2(ull v, float& lo, float& hi) {
    asm("mov.b64 {%0,%1},%2;" : "=f"(lo), "=f"(hi) : "l"(v));
}
__device__ __forceinline__ ull ffma2(ull a, ull b, ull c) {
    ull d; asm("fma.rn.f32x2 %0,%1,%2,%3;" : "=l"(d) : "l"(a), "l"(b), "l"(c)); return d;
}

// ============================================================================
// ENCODER: fused [x_t|h] GEMM + GRU, double-buffered kb=16 pipeline.
// CTA 128 thr = 4 warps; tile 32 rows x 64 u x 3 gates; lane owns u-pair.
// 20 k-blocks: 4 x-part (K=64) then 16 h-part (K=256).
// ============================================================================
struct EncBuf { float in2[16][68]; float wt[16][194]; };

__global__ __launch_bounds__(128, 3)
void enc_step_kernel(const float* __restrict__ x, const float* __restrict__ h0,
                     const float* __restrict__ Wih, const float* __restrict__ Whh,
                     const float* __restrict__ bih, const float* __restrict__ bhh,
                     int t)
{
    __shared__ EncBuf sb[2];
    int tid = threadIdx.x, warp = tid >> 5, lane = tid & 31;
    int bm0 = blockIdx.x * 32, u0 = blockIdx.y * 64;

    const float* h_prev = (t == 0) ? h0 : (g_hs + (size_t)(t - 1) * Bsz * Hh);
    float*  h_out  = g_hs   + (size_t)t * Bsz * Hh;
    __half* hh_out = g_hs_h + (size_t)t * Bsz * Hh;

    const float* xin = x + (size_t)t * Fin + (size_t)bm0 * (Tin * Fin);
    const float* hin = h_prev + (size_t)bm0 * Hh;

    ull aR[8] = {0}, aZ[8] = {0}, aNX[8] = {0}, aNH[8] = {0};

    int kq = tid & 3, row = tid >> 2;       // activation staging coords
    float4 vin; float4 vw[6];

    auto LD = [&](int bi) {
        const float* ip; int ldin; const float* Wp; int ldw; int kb;
        if (bi < 4) { ip = xin; ldin = Tin * Fin; Wp = Wih; ldw = Fin; kb = bi * 16; }
        else        { ip = hin; ldin = Hh;        Wp = Whh; ldw = Hh;  kb = (bi - 4) * 16; }
        vin = *(const float4*)(ip + (size_t)row * ldin + kb + kq * 4);
#pragma unroll
        for (int it = 0; it < 6; ++it) {
            int idx = tid + it * 128; int kw = idx & 3, col = idx >> 2;
            int g = col >> 6, u = col & 63;
            vw[it] = *(const float4*)(Wp + (size_t)(g * 256 + u0 + u) * ldw + kb + kw * 4);
        }
    };
    auto ST = [&](EncBuf& b) {
        *(ull*)&b.in2[kq * 4 + 0][2 * row] = pk2(vin.x, vin.x);
        *(ull*)&b.in2[kq * 4 + 1][2 * row] = pk2(vin.y, vin.y);
        *(ull*)&b.in2[kq * 4 + 2][2 * row] = pk2(vin.z, vin.z);
        *(ull*)&b.in2[kq * 4 + 3][2 * row] = pk2(vin.w, vin.w);
#pragma unroll
        for (int it = 0; it < 6; ++it) {
            int idx = tid + it * 128; int kw = idx & 3, col = idx >> 2;
            b.wt[kw * 4 + 0][col] = vw[it].x;
            b.wt[kw * 4 + 1][col] = vw[it].y;
            b.wt[kw * 4 + 2][col] = vw[it].z;
            b.wt[kw * 4 + 3][col] = vw[it].w;
        }
    };
    auto CP = [&](EncBuf& b, ull (&aN)[8]) {
#pragma unroll
        for (int k = 0; k < 16; ++k) {
            ull w0 = *(const ull*)&b.wt[k][      2 * lane];
            ull w1 = *(const ull*)&b.wt[k][ 64 + 2 * lane];
            ull w2 = *(const ull*)&b.wt[k][128 + 2 * lane];
            const float* ip = &b.in2[k][warp * 16];
            ulonglong2 pA = *(const ulonglong2*)(ip + 0);
            ulonglong2 pB = *(const ulonglong2*)(ip + 4);
            ulonglong2 pC = *(const ulonglong2*)(ip + 8);
            ulonglong2 pD = *(const ulonglong2*)(ip + 12);
            ull v[8] = { pA.x, pA.y, pB.x, pB.y, pC.x, pC.y, pD.x, pD.y };
#pragma unroll
            for (int i = 0; i < 8; ++i) {
                aR[i] = ffma2(v[i], w0, aR[i]);
                aZ[i] = ffma2(v[i], w1, aZ[i]);
                aN[i] = ffma2(v[i], w2, aN[i]);
            }
        }
    };

    LD(0); ST(sb[0]);
#pragma unroll 1
    for (int bi = 0; bi < 4; ++bi) {
        __syncthreads();
        LD(bi + 1);
        CP(sb[bi & 1], aNX);
        ST(sb[(bi + 1) & 1]);
    }
#pragma unroll 1
    for (int bi = 4; bi < 20; ++bi) {
        __syncthreads();
        if (bi < 19) LD(bi + 1);
        CP(sb[bi & 1], aNH);
        if (bi < 19) ST(sb[(bi + 1) & 1]);
    }

    int u = u0 + 2 * lane;
    float2 bir = *(const float2*)&bih[u];
    float2 biz = *(const float2*)&bih[256 + u];
    float2 bin = *(const float2*)&bih[512 + u];
    float2 bhr = *(const float2*)&bhh[u];
    float2 bhz = *(const float2*)&bhh[256 + u];
    float2 bhn = *(const float2*)&bhh[512 + u];
#pragma unroll
    for (int i = 0; i < 8; ++i) {
        int b = bm0 + (warp << 3) + i;
        float r0, r1, z0, z1, nx0, nx1, nh0, nh1;
        upk2(aR[i], r0, r1);  upk2(aZ[i], z0, z1);
        upk2(aNX[i], nx0, nx1); upk2(aNH[i], nh0, nh1);
        float2 hp = *(const float2*)&h_prev[(size_t)b * Hh + u];
        float rr0 = sigm(r0 + bir.x + bhr.x);
        float rr1 = sigm(r1 + bir.y + bhr.y);
        float zz0 = sigm(z0 + biz.x + bhz.x);
        float zz1 = sigm(z1 + biz.y + bhz.y);
        float nn0 = tanh_(nx0 + bin.x + rr0 * (nh0 + bhn.x));
        float nn1 = tanh_(nx1 + bin.y + rr1 * (nh1 + bhn.y));
        float2 o;
        o.x = (1.f - zz0) * nn0 + zz0 * hp.x;
        o.y = (1.f - zz1) * nn1 + zz1 * hp.y;
        *(float2*)&h_out[(size_t)b * Hh + u] = o;
        *(__half2*)&hh_out[(size_t)b * Hh + u] = __float22half2_rn(o);
    }
}

// ---------------- attention precompute: A = Wq.hs, C = bq.hs ----------------
__global__ __launch_bounds__(256)
void attn_pre_kernel(const float* __restrict__ Wq, const float* __restrict__ bq)
{
    int warp = threadIdx.x >> 5, lane = threadIdx.x & 31;
    int p = blockIdx.x * 8 + warp;
    int b = p >> 7, t = p & 127;
    const float* hp = g_hs + ((size_t)t * Bsz + b) * Hh;
    float a = 0.f, c = 0.f;
#pragma unroll
    for (int j = 0; j < 8; ++j) {
        int h = lane + 32 * j;
        float v = hp[h];
        a = fmaf(Wq[h], v, a);
        c = fmaf(bq[h], v, c);
    }
#pragma unroll
    for (int off = 16; off > 0; off >>= 1) {
        a += __shfl_xor_sync(0xffffffffu, a, off);
        c += __shfl_xor_sync(0xffffffffu, c, off);
    }
    if (lane == 0) { g_A[(size_t)b * Tin + t] = a; g_C[(size_t)b * Tin + t] = c; }
}

__global__ void init_prev_kernel(const float* __restrict__ x)
{
    int i = blockIdx.x * 256 + threadIdx.x;
    if (i < Bsz) g_prev[i] = x[(size_t)i * Tin * Fin + (size_t)(Tin - 1) * Fin];
}

// ---------------- decoder attention: softmax + fp16 ctx stream ----------------
// 128 thr, 8 rows/CTA, grid 256. Thread owns h-pair 2*tid.
__global__ __launch_bounds__(128)
void dec_attn_kernel()
{
    __shared__ float wbuf[8][128];
    int tid = threadIdx.x, warp = tid >> 5, lane = tid & 31;
    int b0 = blockIdx.x * 8;
    const float scale = 0.0625f;

#pragma unroll
    for (int rr = 0; rr < 2; ++rr) {
        int r = warp * 2 + rr;
        int b = b0 + r;
        float p = g_prev[b];
        float sv[4]; float m = -1e30f;
#pragma unroll
        for (int j = 0; j < 4; ++j) {
            int t = lane + 32 * j;
            sv[j] = scale * fmaf(p, g_A[(size_t)b * Tin + t], g_C[(size_t)b * Tin + t]);
            m = fmaxf(m, sv[j]);
        }
#pragma unroll
        for (int off = 16; off > 0; off >>= 1)
            m = fmaxf(m, __shfl_xor_sync(0xffffffffu, m, off));
        float sum = 0.f;
#pragma unroll
        for (int j = 0; j < 4; ++j) { sv[j] = __expf(sv[j] - m); sum += sv[j]; }
#pragma unroll
        for (int off = 16; off > 0; off >>= 1)
            sum += __shfl_xor_sync(0xffffffffu, sum, off);
        float inv = 1.f / sum;
#pragma unroll
        for (int j = 0; j < 4; ++j) wbuf[r][lane + 32 * j] = sv[j] * inv;
    }
    __syncthreads();

    float ax[8], ay[8];
#pragma unroll
    for (int r = 0; r < 8; ++r) { ax[r] = 0.f; ay[r] = 0.f; }
#pragma unroll 2
    for (int t = 0; t < Tin; ++t) {
        const __half* hp = g_hs_h + ((size_t)t * Bsz + b0) * Hh + 2 * tid;
#pragma unroll
        for (int r = 0; r < 8; ++r) {
            float w = wbuf[r][t];
            float2 hv = __half22float2(*(const __half2*)(hp + (size_t)r * Hh));
            ax[r] = fmaf(w, hv.x, ax[r]);
            ay[r] = fmaf(w, hv.y, ay[r]);
        }
    }
#pragma unroll
    for (int r = 0; r < 8; ++r) {
        float2 o; o.x = ax[r]; o.y = ay[r];
        *(float2*)&g_ctx[(size_t)(b0 + r) * Hh + 2 * tid] = o;
    }
}

// ---------------- decoder GRU: gh = ctx @ Whh^T (rank-1 gi from prev) ----------------
struct SmemG {
    float in2[32][68];
    float wt [32][194];
};

__global__ __launch_bounds__(128, 3)
void dec_gru_kernel(const float* __restrict__ Wih1, const float* __restrict__ Whh,
                    const float* __restrict__ bih,  const float* __restrict__ bhh)
{
    __shared__ SmemG s;
    int tid = threadIdx.x, warp = tid >> 5, lane = tid & 31;
    int bm0 = blockIdx.x * 32, u0 = blockIdx.y * 64;
    const float* in = g_ctx + (size_t)bm0 * Hh;

    ull aR[8] = {0}, aZ[8] = {0}, aN[8] = {0};
    for (int kb = 0; kb < Hh; kb += 32) {
        __syncthreads();
#pragma unroll
        for (int it = 0; it < 2; ++it) {
            int idx = tid + it * 128;
            int kq8 = idx & 7, row = idx >> 3;
            float4 v = *(const float4*)(in + (size_t)row * Hh + kb + kq8 * 4);
            *(ull*)&s.in2[kq8 * 4 + 0][2 * row] = pk2(v.x, v.x);
            *(ull*)&s.in2[kq8 * 4 + 1][2 * row] = pk2(v.y, v.y);
            *(ull*)&s.in2[kq8 * 4 + 2][2 * row] = pk2(v.z, v.z);
            *(ull*)&s.in2[kq8 * 4 + 3][2 * row] = pk2(v.w, v.w);
        }
#pragma unroll
        for (int it = 0; it < 12; ++it) {
            int idx = tid + it * 128;
            int kq8 = idx & 7, col = idx >> 3;
            int g = col >> 6, u = col & 63;
            float4 v = *(const float4*)(Whh + (size_t)(g * 256 + u0 + u) * Hh + kb + kq8 * 4);
            s.wt[kq8 * 4 + 0][col] = v.x;
            s.wt[kq8 * 4 + 1][col] = v.y;
            s.wt[kq8 * 4 + 2][col] = v.z;
            s.wt[kq8 * 4 + 3][col] = v.w;
        }
        __syncthreads();
#pragma unroll
        for (int k = 0; k < 32; ++k) {
            ull w0 = *(const ull*)&s.wt[k][      2 * lane];
            ull w1 = *(const ull*)&s.wt[k][ 64 + 2 * lane];
            ull w2 = *(const ull*)&s.wt[k][128 + 2 * lane];
            const float* ip = &s.in2[k][warp * 16];
            ulonglong2 pA = *(const ulonglong2*)(ip + 0);
            ulonglong2 pB = *(const ulonglong2*)(ip + 4);
            ulonglong2 pC = *(const ulonglong2*)(ip + 8);
            ulonglong2 pD = *(const ulonglong2*)(ip + 12);
            ull v[8] = { pA.x, pA.y, pB.x, pB.y, pC.x, pC.y, pD.x, pD.y };
#pragma unroll
            for (int i = 0; i < 8; ++i) {
                aR[i] = ffma2(v[i], w0, aR[i]);
                aZ[i] = ffma2(v[i], w1, aZ[i]);
                aN[i] = ffma2(v[i], w2, aN[i]);
            }
        }
    }

    int u = u0 + 2 * lane;
    float2 wir = *(const float2*)&Wih1[u];
    float2 wiz = *(const float2*)&Wih1[256 + u];
    float2 win = *(const float2*)&Wih1[512 + u];
    float2 bir = *(const float2*)&bih[u];
    float2 biz = *(const float2*)&bih[256 + u];
    float2 bin = *(const float2*)&bih[512 + u];
    float2 bhr = *(const float2*)&bhh[u];
    float2 bhz = *(const float2*)&bhh[256 + u];
    float2 bhn = *(const float2*)&bhh[512 + u];
#pragma unroll
    for (int i = 0; i < 8; ++i) {
        int b = bm0 + (warp << 3) + i;
        float p = g_prev[b];
        float hr0, hr1, hz0, hz1, hn0, hn1;
        upk2(aR[i], hr0, hr1); upk2(aZ[i], hz0, hz1); upk2(aN[i], hn0, hn1);
        float2 c = *(const float2*)&g_ctx[(size_t)b * Hh + u];
        float r0 = sigm(fmaf(p, wir.x, bir.x) + hr0 + bhr.x);
        float r1 = sigm(fmaf(p, wir.y, bir.y) + hr1 + bhr.y);
        float z0 = sigm(fmaf(p, wiz.x, biz.x) + hz0 + bhz.x);
        float z1 = sigm(fmaf(p, wiz.y, biz.y) + hz1 + bhz.y);
        float n0 = tanh_(fmaf(p, win.x, bin.x) + r0 * (hn0 + bhn.x));
        float n1 = tanh_(fmaf(p, win.y, bin.y) + r1 * (hn1 + bhn.y));
        float2 o;
        o.x = (1.f - z0) * n0 + z0 * c.x;
        o.y = (1.f - z1) * n1 + z1 * c.y;
        *(float2*)&g_hd[(size_t)b * Hh + u] = o;
    }
}

// ---------------- decoder output: relu(hd@fc1^T+b) @ fc2^T + b ----------------
__global__ __launch_bounds__(256)
void dec_out_kernel(const float* __restrict__ fc1W, const float* __restrict__ fc1b,
                    const float* __restrict__ fc2W, const float* __restrict__ fc2b,
                    float* __restrict__ out, int step)
{
    __shared__ float hds[8][256];
    __shared__ float wsm[32][257];   // pad 257: store banks = k (conflict-free)
    __shared__ float red[8][8];
    int tid = threadIdx.x, warp = tid >> 5, lane = tid & 31;
    int b0 = blockIdx.x * 8;

    for (int idx = tid; idx < 8 * 256; idx += 256) {
        int row = idx >> 8, k = idx & 255;
        hds[row][k] = g_hd[(size_t)(b0 + row) * 256 + k];
    }

    float acc[8] = {0, 0, 0, 0, 0, 0, 0, 0};
    for (int kb = 0; kb < 256; kb += 32) {
        __syncthreads();
        for (int idx = tid; idx < 32 * 256; idx += 256) {
            int j = idx >> 5, k = idx & 31;
            wsm[k][j] = fc1W[(size_t)j * 256 + kb + k];
        }
        __syncthreads();
#pragma unroll
        for (int k = 0; k < 32; ++k) {
            float wv = wsm[k][tid];
#pragma unroll
            for (int r = 0; r < 8; ++r)
                acc[r] = fmaf(hds[r][kb + k], wv, acc[r]);
        }
    }

    float b1 = fc1b[tid];
    float w2 = fc2W[tid];
#pragma unroll
    for (int r = 0; r < 8; ++r) {
        float v = fmaxf(acc[r] + b1, 0.f) * w2;
#pragma unroll
        for (int off = 16; off > 0; off >>= 1)
            v += __shfl_xor_sync(0xffffffffu, v, off);
        if (lane == 0) red[warp][r] = v;
    }
    __syncthreads();
    if (warp == 0 && lane < 8) {
        int r = lane;
        float ssum = 0.f;
#pragma unroll
        for (int w = 0; w < 8; ++w) ssum += red[w][r];
        ssum += fc2b[0];
        int b = b0 + r;
        out[(size_t)b * OUTL + step] = ssum;
        g_prev[b] = ssum;
    }
}

// ---------------- launch ----------------
extern "C" void kernel_launch(void* const* d_in, const int* in_sizes, int n_in,
                              void* d_out, int out_size)
{
    (void)in_sizes; (void)n_in; (void)out_size;
    const float* x    = (const float*)d_in[0];
    const float* h0   = (const float*)d_in[1];
    const float* eWih = (const float*)d_in[2];
    const float* eWhh = (const float*)d_in[3];
    const float* ebih = (const float*)d_in[4];
    const float* ebhh = (const float*)d_in[5];
    const float* dWih = (const float*)d_in[6];
    const float* dWhh = (const float*)d_in[7];
    const float* dbih = (const float*)d_in[8];
    const float* dbhh = (const float*)d_in[9];
    const float* aWq  = (const float*)d_in[10];
    const float* abq  = (const float*)d_in[11];
    const float* f1W  = (const float*)d_in[12];
    const float* f1b  = (const float*)d_in[13];
    const float* f2W  = (const float*)d_in[14];
    const float* f2b  = (const float*)d_in[15];
    float* out = (float*)d_out;

    dim3 gg(Bsz / 32, Hh / 64);   // (64,4) = 256 CTAs, 128 threads

    for (int t = 0; t < Tin; ++t)
        enc_step_kernel<<<gg, 128>>>(x, h0, eWih, eWhh, ebih, ebhh, t);

    attn_pre_kernel<<<(Bsz * Tin) / 8, 256>>>(aWq, abq);
    init_prev_kernel<<<Bsz / 256, 256>>>(x);

    for (int s = 0; s < OUTL; ++s) {
        dec_attn_kernel<<<Bsz / 8, 128>>>();
        dec_gru_kernel<<<gg, 128>>>(dWih, dWhh, dbih, dbhh);
        dec_out_kernel<<<Bsz / 8, 256>>>(f1W, f1b, f2W, f2b, out, s);
    }
}